// round 5
// baseline (speedup 1.0000x reference)
#include <cuda_runtime.h>
#include <cuda_fp16.h>
#include <cuda_fp8.h>
#include <cstdint>

// ---------------- problem dims ----------------
#define B_ 4096
#define I_ 512
#define H_ 1024
#define G4 4096
#define KG 1536   // gates GEMM K (512 + 1024)
#define KC 1024   // cst GEMM K

// ---------------- scratch (device globals; no allocs allowed) ----------------
__device__ float g_gates[(size_t)B_ * G4];
__device__ float g_cst[(size_t)B_ * H_];
__device__ float g_bias[G4];
// gates GEMM operands
__device__ __half  gA_h [(size_t)B_ * KG];   // fp16(A)
__device__ uint8_t gA_l8[(size_t)B_ * KG];   // e4m3((A-Ah)*2048)
__device__ uint8_t gA_f8[(size_t)B_ * KG];   // e4m3(A)
__device__ __half  gW_h [(size_t)G4 * KG];
__device__ uint8_t gW_l8[(size_t)G4 * KG];
__device__ uint8_t gW_f8[(size_t)G4 * KG];
// cst GEMM operands
__device__ __half  gC_h [(size_t)B_ * KC];
__device__ uint8_t gC_l8[(size_t)B_ * KC];
__device__ uint8_t gC_f8[(size_t)B_ * KC];
__device__ __half  gD_h [(size_t)H_ * KC];
__device__ uint8_t gD_l8[(size_t)H_ * KC];
__device__ uint8_t gD_f8[(size_t)H_ * KC];

// ---------------- low-level helpers ----------------
__device__ __forceinline__ uint32_t smem_u32(const void* p) {
    uint32_t a;
    asm("{ .reg .u64 t; cvta.to.shared.u64 t, %1; cvt.u32.u64 %0, t; }" : "=r"(a) : "l"(p));
    return a;
}
__device__ __forceinline__ void cp16(uint32_t dst, const void* src) {
    asm volatile("cp.async.cg.shared.global [%0], [%1], 16;" :: "r"(dst), "l"(src));
}
#define CP_COMMIT() asm volatile("cp.async.commit_group;" ::: "memory")
#define CP_WAIT2()  asm volatile("cp.async.wait_group 2;" ::: "memory")

__device__ __forceinline__ void ldm_x4(uint32_t& r0, uint32_t& r1, uint32_t& r2, uint32_t& r3,
                                       uint32_t addr) {
    asm volatile("ldmatrix.sync.aligned.m8n8.x4.shared.b16 {%0,%1,%2,%3}, [%4];"
                 : "=r"(r0), "=r"(r1), "=r"(r2), "=r"(r3) : "r"(addr));
}
__device__ __forceinline__ void mma_fp16(float* c, const uint32_t* a, const uint32_t* b) {
    asm volatile(
        "mma.sync.aligned.m16n8k16.row.col.f32.f16.f16.f32 "
        "{%0,%1,%2,%3}, {%4,%5,%6,%7}, {%8,%9}, {%0,%1,%2,%3};"
        : "+f"(c[0]), "+f"(c[1]), "+f"(c[2]), "+f"(c[3])
        : "r"(a[0]), "r"(a[1]), "r"(a[2]), "r"(a[3]), "r"(b[0]), "r"(b[1]));
}
__device__ __forceinline__ void mma_fp8(float* c, const uint32_t* a, uint32_t b0, uint32_t b1) {
    asm volatile(
        "mma.sync.aligned.m16n8k32.row.col.f32.e4m3.e4m3.f32 "
        "{%0,%1,%2,%3}, {%4,%5,%6,%7}, {%8,%9}, {%0,%1,%2,%3};"
        : "+f"(c[0]), "+f"(c[1]), "+f"(c[2]), "+f"(c[3])
        : "r"(a[0]), "r"(a[1]), "r"(a[2]), "r"(a[3]), "r"(b0), "r"(b1));
}

// ---------------- GEMM tiling ----------------
// CTA tile 128x128, K-chunk 32. 8 warps: warp m = (wid&3)*32 rows, warp n = (wid>>2)*64 cols.
// fp16 tiles: 128 rows x 64B (+16 pad = 80B stride). fp8 tiles: 128 x 32B (+16 pad = 48B).
#define BKE 32
#define ROWH 80
#define ROW8 48
#define TILEH (128 * ROWH)    // 10240
#define TILE8 (128 * ROW8)    // 6144
#define OFF_AH 0
#define OFF_BH TILEH
#define OFF_AL8 (2 * TILEH)
#define OFF_AF8 (2 * TILEH + TILE8)
#define OFF_BF8 (2 * TILEH + 2 * TILE8)
#define OFF_BL8 (2 * TILEH + 3 * TILE8)
#define STAGEB (2 * TILEH + 4 * TILE8)   // 45056
#define NSTG 3
#define SMEM_DYN (NSTG * STAGEB)         // 135168

#define INV2048 4.8828125e-4f

// One stage: fp16 tiles (2 cp16/thread each), fp8 tiles (1 cp16/thread each) = 8 cp16/thread.
__device__ __forceinline__ void load_stage(
    uint32_t sb,
    const __half* __restrict__ Ah, const __half* __restrict__ Bh,
    const uint8_t* __restrict__ Al8, const uint8_t* __restrict__ Af8,
    const uint8_t* __restrict__ Bf8, const uint8_t* __restrict__ Bl8,
    int mBase, int nBase, int k0, int Ktot, int tid)
{
    // fp16 tiles: 512 chunks of 16B each
    #pragma unroll
    for (int i = 0; i < 2; ++i) {
        const int id  = tid + i * 256;
        const int row = id >> 2;
        const int c   = id & 3;
        const uint32_t doff = row * ROWH + c * 16;
        cp16(sb + OFF_AH + doff, (const char*)(Ah + (size_t)(mBase + row) * Ktot + k0) + c * 16);
        cp16(sb + OFF_BH + doff, (const char*)(Bh + (size_t)(nBase + row) * Ktot + k0) + c * 16);
    }
    // fp8 tiles: 256 chunks of 16B each
    {
        const int row = tid >> 1;
        const int c   = tid & 1;
        const uint32_t doff = row * ROW8 + c * 16;
        const size_t aoff = (size_t)(mBase + row) * Ktot + k0 + c * 16;
        const size_t boff = (size_t)(nBase + row) * Ktot + k0 + c * 16;
        cp16(sb + OFF_AL8 + doff, Al8 + aoff);
        cp16(sb + OFF_AF8 + doff, Af8 + aoff);
        cp16(sb + OFF_BF8 + doff, Bf8 + boff);
        cp16(sb + OFF_BL8 + doff, Bl8 + boff);
    }
}

// act==0: C = D + bias[n]      act==1: C = tanh(D + bias[n])
__global__ __launch_bounds__(256) void tc_gemm_kernel(
    const __half* __restrict__ Ah, const __half* __restrict__ Bh,
    const uint8_t* __restrict__ Al8, const uint8_t* __restrict__ Af8,
    const uint8_t* __restrict__ Bf8, const uint8_t* __restrict__ Bl8,
    int Ktot, int ldC, const float* __restrict__ bias, int act,
    float* __restrict__ C)
{
    extern __shared__ char smem[];
    const uint32_t smem_base = smem_u32(smem);
    const int tid = threadIdx.x;
    const int wid = tid >> 5, lane = tid & 31;
    const int wm = (wid & 3) * 32;
    const int wn = (wid >> 2) * 64;
    const int mBase = blockIdx.y * 128, nBase = blockIdx.x * 128;

    float acc[2][8][4];    // fp16 main term
    float acc2[2][8][4];   // fp8 corrections (scale 2^-11)
    #pragma unroll
    for (int i = 0; i < 2; ++i)
        #pragma unroll
        for (int j = 0; j < 8; ++j)
            #pragma unroll
            for (int q = 0; q < 4; ++q) { acc[i][j][q] = 0.0f; acc2[i][j][q] = 0.0f; }

    const int nchunks = Ktot / BKE;

    load_stage(smem_base, Ah, Bh, Al8, Af8, Bf8, Bl8, mBase, nBase, 0, Ktot, tid);
    CP_COMMIT();
    load_stage(smem_base + STAGEB, Ah, Bh, Al8, Af8, Bf8, Bl8, mBase, nBase, BKE, Ktot, tid);
    CP_COMMIT();

    // fp16 ldmatrix addressing (validated in R3)
    const int aRowH = wm + (lane & 15);
    const int aColH = (lane & 16);
    const int bRowH = wn + (lane & 7) + ((lane & 16) >> 1);
    const int bColH = (lane & 8) << 1;
    // fp8 ldmatrix addressing: row = lane&15 (+tile offset), byte col = lane&16
    const int row8 = (lane & 15);
    const int col8 = (lane & 16);

    int buf = 0;
    for (int c = 0; c < nchunks; ++c) {
        {
            const int nb = (buf + 2 >= NSTG) ? buf + 2 - NSTG : buf + 2;
            if (c + 2 < nchunks)
                load_stage(smem_base + nb * STAGEB, Ah, Bh, Al8, Af8, Bf8, Bl8,
                           mBase, nBase, (c + 2) * BKE, Ktot, tid);
            CP_COMMIT();
        }
        CP_WAIT2();
        __syncthreads();

        const uint32_t sb = smem_base + buf * STAGEB;

        // ---- fp16 main term (two k16 steps) ----
        #pragma unroll
        for (int ks = 0; ks < 2; ++ks) {
            const int kb = ks * 32;
            uint32_t ah[2][4], bh[4][4];
            #pragma unroll
            for (int mt = 0; mt < 2; ++mt) {
                const uint32_t ad = sb + OFF_AH + (aRowH + mt * 16) * ROWH + kb + aColH;
                ldm_x4(ah[mt][0], ah[mt][1], ah[mt][2], ah[mt][3], ad);
            }
            #pragma unroll
            for (int nt = 0; nt < 4; ++nt) {
                const uint32_t bd = sb + OFF_BH + (bRowH + nt * 16) * ROWH + kb + bColH;
                ldm_x4(bh[nt][0], bh[nt][1], bh[nt][2], bh[nt][3], bd);
            }
            #pragma unroll
            for (int mt = 0; mt < 2; ++mt)
                #pragma unroll
                for (int nt = 0; nt < 8; ++nt)
                    mma_fp16(acc[mt][nt], ah[mt], &bh[nt >> 1][(nt & 1) * 2]);
        }

        // ---- fp8 correction term 2: Al*B (one k32 step) ----
        {
            uint32_t a8[2][4], b8[4][4];
            #pragma unroll
            for (int mt = 0; mt < 2; ++mt) {
                const uint32_t ad = sb + OFF_AL8 + (wm + mt * 16 + row8) * ROW8 + col8;
                ldm_x4(a8[mt][0], a8[mt][1], a8[mt][2], a8[mt][3], ad);
            }
            #pragma unroll
            for (int nt = 0; nt < 4; ++nt) {
                const uint32_t bd = sb + OFF_BF8 + (wn + nt * 16 + row8) * ROW8 + col8;
                ldm_x4(b8[nt][0], b8[nt][1], b8[nt][2], b8[nt][3], bd);
            }
            #pragma unroll
            for (int mt = 0; mt < 2; ++mt)
                #pragma unroll
                for (int nt = 0; nt < 8; ++nt)
                    mma_fp8(acc2[mt][nt], a8[mt],
                            b8[nt >> 1][nt & 1], b8[nt >> 1][(nt & 1) + 2]);
        }
        // ---- fp8 correction term 3: A*Bl ----
        {
            uint32_t a8[2][4], b8[4][4];
            #pragma unroll
            for (int mt = 0; mt < 2; ++mt) {
                const uint32_t ad = sb + OFF_AF8 + (wm + mt * 16 + row8) * ROW8 + col8;
                ldm_x4(a8[mt][0], a8[mt][1], a8[mt][2], a8[mt][3], ad);
            }
            #pragma unroll
            for (int nt = 0; nt < 4; ++nt) {
                const uint32_t bd = sb + OFF_BL8 + (wn + nt * 16 + row8) * ROW8 + col8;
                ldm_x4(b8[nt][0], b8[nt][1], b8[nt][2], b8[nt][3], bd);
            }
            #pragma unroll
            for (int mt = 0; mt < 2; ++mt)
                #pragma unroll
                for (int nt = 0; nt < 8; ++nt)
                    mma_fp8(acc2[mt][nt], a8[mt],
                            b8[nt >> 1][nt & 1], b8[nt >> 1][(nt & 1) + 2]);
        }

        __syncthreads();
        buf = (buf + 1 == NSTG) ? 0 : buf + 1;
    }

    // epilogue
    const int rq = lane >> 2, cq = (lane & 3) * 2;
    #pragma unroll
    for (int mt = 0; mt < 2; ++mt) {
        const int row0 = mBase + wm + mt * 16 + rq;
        #pragma unroll
        for (int nt = 0; nt < 8; ++nt) {
            const int col = nBase + wn + nt * 8 + cq;
            const float b0 = bias[col], b1 = bias[col + 1];
            float2 v0, v1;
            v0.x = acc[mt][nt][0] + acc2[mt][nt][0] * INV2048 + b0;
            v0.y = acc[mt][nt][1] + acc2[mt][nt][1] * INV2048 + b1;
            v1.x = acc[mt][nt][2] + acc2[mt][nt][2] * INV2048 + b0;
            v1.y = acc[mt][nt][3] + acc2[mt][nt][3] * INV2048 + b1;
            if (act) {
                v0.x = tanhf(v0.x); v0.y = tanhf(v0.y);
                v1.x = tanhf(v1.x); v1.y = tanhf(v1.y);
            }
            *(float2*)&C[(size_t)row0 * ldC + col]       = v0;
            *(float2*)&C[(size_t)(row0 + 8) * ldC + col] = v1;
        }
    }
}

// ---------------- conversion / packing ----------------
__device__ __forceinline__ uint8_t to_e4m3(float v) {
    return (uint8_t)__nv_cvt_float_to_fp8(v, __NV_SATFINITE, __NV_E4M3);
}
__device__ __forceinline__ void split3(float v, __half& h, uint8_t& l8, uint8_t& f8) {
    h = __float2half(v);
    const float r = v - __half2float(h);
    l8 = to_e4m3(r * 2048.0f);
    f8 = to_e4m3(v);
}

// rows of [K1 | K2] from (s1, s2) -> (h, l8, f8), row stride KG
__global__ __launch_bounds__(256) void pack2_kernel(
    const float* __restrict__ s1, const float* __restrict__ s2,
    __half* __restrict__ h, uint8_t* __restrict__ l8, uint8_t* __restrict__ f8)
{
    const int row = blockIdx.x;
    #pragma unroll
    for (int i = 0; i < KG / 256; ++i) {
        const int k = threadIdx.x + i * 256;
        const float v = (k < I_) ? s1[(size_t)row * I_ + k]
                                 : s2[(size_t)row * H_ + (k - I_)];
        __half hh; uint8_t ll, ff; split3(v, hh, ll, ff);
        h [(size_t)row * KG + k] = hh;
        l8[(size_t)row * KG + k] = ll;
        f8[(size_t)row * KG + k] = ff;
    }
}

__global__ __launch_bounds__(256) void pack1_kernel(
    const float* __restrict__ src,
    __half* __restrict__ h, uint8_t* __restrict__ l8, uint8_t* __restrict__ f8)
{
    const int row = blockIdx.x;
    #pragma unroll
    for (int i = 0; i < KC / 256; ++i) {
        const int k = threadIdx.x + i * 256;
        const float v = src[(size_t)row * KC + k];
        __half hh; uint8_t ll, ff; split3(v, hh, ll, ff);
        h [(size_t)row * KC + k] = hh;
        l8[(size_t)row * KC + k] = ll;
        f8[(size_t)row * KC + k] = ff;
    }
}

// out[n, k] = W[k, n]  (transpose + split), W is [H_, H_]
__global__ void pack_transpose_kernel(const float* __restrict__ W,
                                      __half* __restrict__ h,
                                      uint8_t* __restrict__ l8, uint8_t* __restrict__ f8)
{
    __shared__ float tile[32][33];
    const int bx = blockIdx.x * 32, by = blockIdx.y * 32;
    const int tx = threadIdx.x, ty = threadIdx.y;   // 32 x 8
    #pragma unroll
    for (int i = 0; i < 32; i += 8)
        tile[ty + i][tx] = W[(size_t)(by + ty + i) * H_ + bx + tx];
    __syncthreads();
    #pragma unroll
    for (int i = 0; i < 32; i += 8) {
        const float v = tile[tx][ty + i];
        __half hh; uint8_t ll, ff; split3(v, hh, ll, ff);
        const size_t o = (size_t)(bx + ty + i) * KC + by + tx;
        h[o] = hh; l8[o] = ll; f8[o] = ff;
    }
}

__global__ __launch_bounds__(256) void bias_kernel(const float* __restrict__ b1,
                                                   const float* __restrict__ b2,
                                                   float* __restrict__ out) {
    const int i = blockIdx.x * 256 + threadIdx.x;
    out[i] = b1[i] + b2[i];
}

// ---------------- T-LSTM elementwise epilogue ----------------
__device__ __forceinline__ float sigmoidf_(float x) { return 1.0f / (1.0f + expf(-x)); }

__global__ __launch_bounds__(256) void tlstm_epilogue_kernel(
    const float* __restrict__ tvec, const float* __restrict__ cx, float* __restrict__ out)
{
    const int idx = blockIdx.x * blockDim.x + threadIdx.x;  // < B*H
    const int b = idx >> 10;
    const float tb = tvec[b];
    const float T = (tb != 0.0f) ? (1.0f / tb) : 0.0f;

    const float* grow = g_gates + (size_t)b * G4 + (idx & (H_ - 1));
    const float ig = grow[0];
    const float fg = grow[H_];
    const float cg = grow[2 * H_];
    const float og = grow[3 * H_];

    const float cst  = g_cst[idx];
    const float c    = cx[idx];
    const float cadj = c - cst + T * cst;

    const float cy = sigmoidf_(fg) * cadj + sigmoidf_(ig) * tanhf(cg);
    const float hy = sigmoidf_(og) * tanhf(cy);

    out[idx] = hy;
    out[(size_t)B_ * H_ + idx] = cy;
}

// ---------------- launch ----------------
extern "C" void kernel_launch(void* const* d_in, const int* in_sizes, int n_in,
                              void* d_out, int out_size) {
    const float* input     = (const float*)d_in[0];
    const float* t         = (const float*)d_in[1];
    const float* hx        = (const float*)d_in[2];
    const float* cx        = (const float*)d_in[3];
    const float* weight_ih = (const float*)d_in[4];
    const float* weight_hh = (const float*)d_in[5];
    const float* bias_ih   = (const float*)d_in[6];
    const float* bias_hh   = (const float*)d_in[7];
    const float* W_decomp  = (const float*)d_in[8];
    const float* b_decomp  = (const float*)d_in[9];
    float* out = (float*)d_out;

    float *gates_p, *cst_p, *bias_p;
    __half *Ah, *Wh, *Ch, *Dh;
    uint8_t *Al8, *Af8, *Wl8, *Wf8, *Cl8, *Cf8, *Dl8, *Df8;
    cudaGetSymbolAddress((void**)&gates_p, g_gates);
    cudaGetSymbolAddress((void**)&cst_p, g_cst);
    cudaGetSymbolAddress((void**)&bias_p, g_bias);
    cudaGetSymbolAddress((void**)&Ah, gA_h);
    cudaGetSymbolAddress((void**)&Al8, gA_l8);
    cudaGetSymbolAddress((void**)&Af8, gA_f8);
    cudaGetSymbolAddress((void**)&Wh, gW_h);
    cudaGetSymbolAddress((void**)&Wl8, gW_l8);
    cudaGetSymbolAddress((void**)&Wf8, gW_f8);
    cudaGetSymbolAddress((void**)&Ch, gC_h);
    cudaGetSymbolAddress((void**)&Cl8, gC_l8);
    cudaGetSymbolAddress((void**)&Cf8, gC_f8);
    cudaGetSymbolAddress((void**)&Dh, gD_h);
    cudaGetSymbolAddress((void**)&Dl8, gD_l8);
    cudaGetSymbolAddress((void**)&Df8, gD_f8);

    cudaFuncSetAttribute(tc_gemm_kernel, cudaFuncAttributeMaxDynamicSharedMemorySize, SMEM_DYN);

    pack2_kernel<<<B_, 256>>>(input, hx, Ah, Al8, Af8);
    pack2_kernel<<<G4, 256>>>(weight_ih, weight_hh, Wh, Wl8, Wf8);
    pack1_kernel<<<B_, 256>>>(cx, Ch, Cl8, Cf8);
    pack_transpose_kernel<<<dim3(H_ / 32, H_ / 32), dim3(32, 8)>>>(W_decomp, Dh, Dl8, Df8);
    bias_kernel<<<G4 / 256, 256>>>(bias_ih, bias_hh, bias_p);

    // gates: [4096 x 4096]
    tc_gemm_kernel<<<dim3(G4 / 128, B_ / 128), 256, SMEM_DYN>>>(
        Ah, Wh, Al8, Af8, Wf8, Wl8, KG, G4, bias_p, 0, gates_p);

    // C_ST: [4096 x 1024] = tanh(cx @ Wd^T + b_decomp)
    tc_gemm_kernel<<<dim3(H_ / 128, B_ / 128), 256, SMEM_DYN>>>(
        Ch, Dh, Cl8, Cf8, Df8, Dl8, KC, H_, b_decomp, 1, cst_p);

    tlstm_epilogue_kernel<<<(B_ * H_) / 256, 256>>>(t, cx, out);
}

// round 6
// speedup vs baseline: 1.3387x; 1.3387x over previous
#include <cuda_runtime.h>
#include <cuda_bf16.h>
#include <cstdint>

// ---------------- problem dims ----------------
#define B_ 4096
#define I_ 512
#define H_ 1024
#define G4 4096
#define KG 1536   // gates GEMM K (512 + 1024)
#define KC 1024   // cst GEMM K

// ---------------- scratch (device globals; no allocs allowed) ----------------
__device__ float g_cst[(size_t)B_ * H_];
__device__ float g_bias[G4];                      // interleaved bias
__device__ __nv_bfloat16 gA_hi[(size_t)B_ * KG];
__device__ __nv_bfloat16 gA_lo[(size_t)B_ * KG];
__device__ __nv_bfloat16 gW_hi[(size_t)G4 * KG]; // interleaved rows n' = 4h+g
__device__ __nv_bfloat16 gW_lo[(size_t)G4 * KG];
__device__ __nv_bfloat16 gCx_hi[(size_t)B_ * KC];
__device__ __nv_bfloat16 gCx_lo[(size_t)B_ * KC];
__device__ __nv_bfloat16 gWd_hi[(size_t)H_ * KC];
__device__ __nv_bfloat16 gWd_lo[(size_t)H_ * KC];

// ---------------- low-level helpers ----------------
__device__ __forceinline__ uint32_t smem_u32(const void* p) {
    uint32_t a;
    asm("{ .reg .u64 t; cvta.to.shared.u64 t, %1; cvt.u32.u64 %0, t; }" : "=r"(a) : "l"(p));
    return a;
}
__device__ __forceinline__ void cp16(uint32_t dst, const void* src) {
    asm volatile("cp.async.cg.shared.global [%0], [%1], 16;" :: "r"(dst), "l"(src));
}
#define CP_COMMIT() asm volatile("cp.async.commit_group;" ::: "memory")
#define CP_WAIT2()  asm volatile("cp.async.wait_group 2;" ::: "memory")

__device__ __forceinline__ void ldm_x4(uint32_t& r0, uint32_t& r1, uint32_t& r2, uint32_t& r3,
                                       uint32_t addr) {
    asm volatile("ldmatrix.sync.aligned.m8n8.x4.shared.b16 {%0,%1,%2,%3}, [%4];"
                 : "=r"(r0), "=r"(r1), "=r"(r2), "=r"(r3) : "r"(addr));
}
__device__ __forceinline__ void mma_bf16(float* c, const uint32_t* a, const uint32_t* b) {
    asm volatile(
        "mma.sync.aligned.m16n8k16.row.col.f32.bf16.bf16.f32 "
        "{%0,%1,%2,%3}, {%4,%5,%6,%7}, {%8,%9}, {%0,%1,%2,%3};"
        : "+f"(c[0]), "+f"(c[1]), "+f"(c[2]), "+f"(c[3])
        : "r"(a[0]), "r"(a[1]), "r"(a[2]), "r"(a[3]), "r"(b[0]), "r"(b[1]));
}
__device__ __forceinline__ float sigmoidf_(float x) { return 1.0f / (1.0f + expf(-x)); }

// ---------------- GEMM tiling ----------------
// CTA tile 128x128, BKE=64 (bf16, 128B/row + 16B pad). 16 warps (512 thr), warp tile 32x32.
#define BKE 64
#define ROWB 144
#define TILEB (128 * ROWB)   // 18432
#define OFF_AH 0
#define OFF_AL TILEB
#define OFF_BH (2 * TILEB)
#define OFF_BL (3 * TILEB)
#define STAGEB (4 * TILEB)   // 73728
#define NSTG 3
#define SMEM_DYN (NSTG * STAGEB)   // 221184

// One stage: 4 tiles x 1024 cp16 chunks / 512 threads = 8 cp16 per thread.
__device__ __forceinline__ void load_stage(
    uint32_t sb,
    const __nv_bfloat16* __restrict__ Ahi, const __nv_bfloat16* __restrict__ Alo,
    const __nv_bfloat16* __restrict__ Bhi, const __nv_bfloat16* __restrict__ Blo,
    int mBase, int nBase, int k0, int Ktot, int tid)
{
    #pragma unroll
    for (int i = 0; i < 2; ++i) {
        const int id  = tid + i * 512;      // 0..1023
        const int row = id >> 3;            // 0..127
        const int c   = id & 7;             // 16B chunk within 128B row
        const uint32_t doff = row * ROWB + c * 16;
        const size_t aoff = (size_t)(mBase + row) * Ktot + k0 + c * 8;
        const size_t boff = (size_t)(nBase + row) * Ktot + k0 + c * 8;
        cp16(sb + OFF_AH + doff, Ahi + aoff);
        cp16(sb + OFF_AL + doff, Alo + aoff);
        cp16(sb + OFF_BH + doff, Bhi + boff);
        cp16(sb + OFF_BL + doff, Blo + boff);
    }
}

// FUSED=false: C[row, col] = tanh(D + bias[col])        (cst GEMM, ldC = H_)
// FUSED=true : full T-LSTM epilogue; weights interleaved n'=4h+g; writes hy/cy to C.
template <bool FUSED>
__global__ __launch_bounds__(512, 1) void tc_gemm_kernel(
    const __nv_bfloat16* __restrict__ Ahi, const __nv_bfloat16* __restrict__ Alo,
    const __nv_bfloat16* __restrict__ Bhi, const __nv_bfloat16* __restrict__ Blo,
    int Ktot, int ldC, const float* __restrict__ bias,
    const float* __restrict__ tvec, const float* __restrict__ cx,
    const float* __restrict__ cst,
    float* __restrict__ C)
{
    extern __shared__ char smem[];
    const uint32_t smem_base = smem_u32(smem);
    const int tid = threadIdx.x;
    const int wid = tid >> 5, lane = tid & 31;
    const int wm = (wid & 3) * 32;       // warp row offset
    const int wn = (wid >> 2) * 32;      // warp col offset
    const int mBase = blockIdx.y * 128, nBase = blockIdx.x * 128;

    float acc[2][4][4];
    #pragma unroll
    for (int i = 0; i < 2; ++i)
        #pragma unroll
        for (int j = 0; j < 4; ++j)
            #pragma unroll
            for (int q = 0; q < 4; ++q) acc[i][j][q] = 0.0f;

    const int nchunks = Ktot / BKE;

    load_stage(smem_base, Ahi, Alo, Bhi, Blo, mBase, nBase, 0, Ktot, tid);
    CP_COMMIT();
    load_stage(smem_base + STAGEB, Ahi, Alo, Bhi, Blo, mBase, nBase, BKE, Ktot, tid);
    CP_COMMIT();

    // ldmatrix per-lane addressing (validated in R3)
    const int aRow = wm + (lane & 15);
    const int aCol = (lane & 16);
    const int bRow = wn + (lane & 7) + ((lane & 16) >> 1);
    const int bCol = (lane & 8) << 1;

    int buf = 0;
    for (int c = 0; c < nchunks; ++c) {
        {
            const int nb = (buf + 2 >= NSTG) ? buf + 2 - NSTG : buf + 2;
            if (c + 2 < nchunks)
                load_stage(smem_base + nb * STAGEB, Ahi, Alo, Bhi, Blo,
                           mBase, nBase, (c + 2) * BKE, Ktot, tid);
            CP_COMMIT();
        }
        CP_WAIT2();
        __syncthreads();

        const uint32_t sb = smem_base + buf * STAGEB;
        #pragma unroll
        for (int ks = 0; ks < 4; ++ks) {
            const int kb = ks * 32;
            uint32_t ah[2][4], al[2][4], bh[2][4], bl[2][4];
            #pragma unroll
            for (int mt = 0; mt < 2; ++mt) {
                const uint32_t ad = sb + (aRow + mt * 16) * ROWB + kb + aCol;
                ldm_x4(ah[mt][0], ah[mt][1], ah[mt][2], ah[mt][3], ad + OFF_AH);
                ldm_x4(al[mt][0], al[mt][1], al[mt][2], al[mt][3], ad + OFF_AL);
            }
            #pragma unroll
            for (int nt = 0; nt < 2; ++nt) {
                const uint32_t bd = sb + (bRow + nt * 16) * ROWB + kb + bCol;
                ldm_x4(bh[nt][0], bh[nt][1], bh[nt][2], bh[nt][3], bd + OFF_BH);
                ldm_x4(bl[nt][0], bl[nt][1], bl[nt][2], bl[nt][3], bd + OFF_BL);
            }
            #pragma unroll
            for (int mt = 0; mt < 2; ++mt)
                #pragma unroll
                for (int nt = 0; nt < 4; ++nt)
                    mma_bf16(acc[mt][nt], ah[mt], &bh[nt >> 1][(nt & 1) * 2]);
            #pragma unroll
            for (int mt = 0; mt < 2; ++mt)
                #pragma unroll
                for (int nt = 0; nt < 4; ++nt)
                    mma_bf16(acc[mt][nt], al[mt], &bh[nt >> 1][(nt & 1) * 2]);
            #pragma unroll
            for (int mt = 0; mt < 2; ++mt)
                #pragma unroll
                for (int nt = 0; nt < 4; ++nt)
                    mma_bf16(acc[mt][nt], ah[mt], &bl[nt >> 1][(nt & 1) * 2]);
        }
        __syncthreads();
        buf = (buf + 1 == NSTG) ? 0 : buf + 1;
    }

    const int rq = lane >> 2, cq = (lane & 3) * 2;

    if (!FUSED) {
        #pragma unroll
        for (int mt = 0; mt < 2; ++mt) {
            const int row0 = mBase + wm + mt * 16 + rq;
            #pragma unroll
            for (int nt = 0; nt < 4; ++nt) {
                const int col = nBase + wn + nt * 8 + cq;
                const float b0 = bias[col], b1 = bias[col + 1];
                float2 v0 = make_float2(tanhf(acc[mt][nt][0] + b0), tanhf(acc[mt][nt][1] + b1));
                float2 v1 = make_float2(tanhf(acc[mt][nt][2] + b0), tanhf(acc[mt][nt][3] + b1));
                *(float2*)&C[(size_t)row0 * ldC + col]       = v0;
                *(float2*)&C[(size_t)(row0 + 8) * ldC + col] = v1;
            }
        }
    } else {
        // Fused T-LSTM epilogue. Columns n' = 4h+g. Lane pairs (even,odd) jointly
        // hold (i,f) and (c,o) of the same h; exchange via shfl so even handles
        // row rq, odd handles row rq+8. Stage hy/cy in smem, then coalesced store.
        float* s_hy = (float*)smem;             // [128][33]
        float* s_cy = s_hy + 128 * 33;
        __syncthreads();                        // mainloop smem dead; safe to reuse

        const bool even = !(lane & 1);
        #pragma unroll
        for (int mt = 0; mt < 2; ++mt) {
            #pragma unroll
            for (int nt = 0; nt < 4; ++nt) {
                const int n0 = nBase + wn + nt * 8 + cq;
                const float b0 = bias[n0], b1 = bias[n0 + 1];
                const float c0 = acc[mt][nt][0] + b0, c1 = acc[mt][nt][1] + b1;
                const float c2 = acc[mt][nt][2] + b0, c3 = acc[mt][nt][3] + b1;
                const float x = __shfl_xor_sync(0xffffffffu, even ? c2 : c0, 1);
                const float y = __shfl_xor_sync(0xffffffffu, even ? c3 : c1, 1);
                float ig, fg, cg, og;
                if (even) { ig = c0; fg = c1; cg = x;  og = y;  }
                else      { ig = x;  fg = y;  cg = c2; og = c3; }
                const int row_l = wm + mt * 16 + rq + (even ? 0 : 8);
                const int h_loc = (wn + nt * 8 + (cq & 4)) >> 2;
                const int row = mBase + row_l;
                const int h = (nBase >> 2) + h_loc;

                const float tb = tvec[row];
                const float T = (tb != 0.0f) ? (1.0f / tb) : 0.0f;
                const float cs = cst[(size_t)row * H_ + h];
                const float cc = cx[(size_t)row * H_ + h];
                const float cadj = cc - cs + T * cs;
                const float cyv = sigmoidf_(fg) * cadj + sigmoidf_(ig) * tanhf(cg);
                const float hyv = sigmoidf_(og) * tanhf(cyv);
                s_hy[row_l * 33 + h_loc] = hyv;
                s_cy[row_l * 33 + h_loc] = cyv;
            }
        }
        __syncthreads();
        #pragma unroll
        for (int i = 0; i < 8; ++i) {
            const int idx = tid + i * 512;      // 0..4095
            const int r = idx >> 5, hh = idx & 31;
            const size_t o = (size_t)(mBase + r) * H_ + (nBase >> 2) + hh;
            C[o] = s_hy[r * 33 + hh];
            C[(size_t)B_ * H_ + o] = s_cy[r * 33 + hh];
        }
    }
}

// ---------------- conversion / packing kernels ----------------
__device__ __forceinline__ void split_bf16(float v, __nv_bfloat16& h, __nv_bfloat16& l) {
    h = __float2bfloat16(v);
    l = __float2bfloat16(v - __bfloat162float(h));
}

// A rows: [input | hx], row stride KG
__global__ __launch_bounds__(256) void pack_a_kernel(
    const float* __restrict__ s1, const float* __restrict__ s2,
    __nv_bfloat16* __restrict__ hi, __nv_bfloat16* __restrict__ lo)
{
    const int row = blockIdx.x;
    #pragma unroll
    for (int i = 0; i < KG / 256; ++i) {
        const int k = threadIdx.x + i * 256;
        const float v = (k < I_) ? s1[(size_t)row * I_ + k]
                                 : s2[(size_t)row * H_ + (k - I_)];
        __nv_bfloat16 h, l; split_bf16(v, h, l);
        hi[(size_t)row * KG + k] = h;
        lo[(size_t)row * KG + k] = l;
    }
}

// Interleaved gate weights: row n' = 4h+g <- concat(w_ih, w_hh) row g*1024+h
__global__ __launch_bounds__(256) void pack_w_kernel(
    const float* __restrict__ w_ih, const float* __restrict__ w_hh,
    __nv_bfloat16* __restrict__ hi, __nv_bfloat16* __restrict__ lo)
{
    const int np = blockIdx.x;          // 0..4095
    const int g = np & 3, j = np >> 2;
    const int src = g * H_ + j;
    #pragma unroll
    for (int i = 0; i < KG / 256; ++i) {
        const int k = threadIdx.x + i * 256;
        const float v = (k < I_) ? w_ih[(size_t)src * I_ + k]
                                 : w_hh[(size_t)src * H_ + (k - I_)];
        __nv_bfloat16 h, l; split_bf16(v, h, l);
        hi[(size_t)np * KG + k] = h;
        lo[(size_t)np * KG + k] = l;
    }
}

__global__ __launch_bounds__(256) void pack_cx_kernel(
    const float* __restrict__ src,
    __nv_bfloat16* __restrict__ hi, __nv_bfloat16* __restrict__ lo)
{
    const int row = blockIdx.x;
    #pragma unroll
    for (int i = 0; i < KC / 256; ++i) {
        const int k = threadIdx.x + i * 256;
        const float v = src[(size_t)row * KC + k];
        __nv_bfloat16 h, l; split_bf16(v, h, l);
        hi[(size_t)row * KC + k] = h;
        lo[(size_t)row * KC + k] = l;
    }
}

// out[n, k] = W[k, n]  (transpose + split), W is [H_, H_]
__global__ void pack_transpose_kernel(const float* __restrict__ W,
                                      __nv_bfloat16* __restrict__ hi,
                                      __nv_bfloat16* __restrict__ lo)
{
    __shared__ float tile[32][33];
    const int bx = blockIdx.x * 32, by = blockIdx.y * 32;
    const int tx = threadIdx.x, ty = threadIdx.y;   // 32 x 8
    #pragma unroll
    for (int i = 0; i < 32; i += 8)
        tile[ty + i][tx] = W[(size_t)(by + ty + i) * H_ + bx + tx];
    __syncthreads();
    #pragma unroll
    for (int i = 0; i < 32; i += 8) {
        const float v = tile[tx][ty + i];
        __nv_bfloat16 h, l; split_bf16(v, h, l);
        hi[(size_t)(bx + ty + i) * KC + by + tx] = h;
        lo[(size_t)(bx + ty + i) * KC + by + tx] = l;
    }
}

// Interleaved bias: b'[4h+g] = bias_ih[g*1024+h] + bias_hh[g*1024+h]
__global__ __launch_bounds__(256) void bias_kernel(const float* __restrict__ b1,
                                                   const float* __restrict__ b2,
                                                   float* __restrict__ out) {
    const int np = blockIdx.x * 256 + threadIdx.x;
    const int src = (np & 3) * H_ + (np >> 2);
    out[np] = b1[src] + b2[src];
}

// ---------------- launch ----------------
extern "C" void kernel_launch(void* const* d_in, const int* in_sizes, int n_in,
                              void* d_out, int out_size) {
    const float* input     = (const float*)d_in[0];
    const float* t         = (const float*)d_in[1];
    const float* hx        = (const float*)d_in[2];
    const float* cx        = (const float*)d_in[3];
    const float* weight_ih = (const float*)d_in[4];
    const float* weight_hh = (const float*)d_in[5];
    const float* bias_ih   = (const float*)d_in[6];
    const float* bias_hh   = (const float*)d_in[7];
    const float* W_decomp  = (const float*)d_in[8];
    const float* b_decomp  = (const float*)d_in[9];
    float* out = (float*)d_out;

    float *cst_p, *bias_p;
    __nv_bfloat16 *ah, *al, *wh, *wl, *ch, *cl, *dh, *dl;
    cudaGetSymbolAddress((void**)&cst_p, g_cst);
    cudaGetSymbolAddress((void**)&bias_p, g_bias);
    cudaGetSymbolAddress((void**)&ah, gA_hi);
    cudaGetSymbolAddress((void**)&al, gA_lo);
    cudaGetSymbolAddress((void**)&wh, gW_hi);
    cudaGetSymbolAddress((void**)&wl, gW_lo);
    cudaGetSymbolAddress((void**)&ch, gCx_hi);
    cudaGetSymbolAddress((void**)&cl, gCx_lo);
    cudaGetSymbolAddress((void**)&dh, gWd_hi);
    cudaGetSymbolAddress((void**)&dl, gWd_lo);

    cudaFuncSetAttribute(tc_gemm_kernel<false>,
                         cudaFuncAttributeMaxDynamicSharedMemorySize, SMEM_DYN);
    cudaFuncSetAttribute(tc_gemm_kernel<true>,
                         cudaFuncAttributeMaxDynamicSharedMemorySize, SMEM_DYN);

    // packs
    pack_a_kernel<<<B_, 256>>>(input, hx, ah, al);
    pack_w_kernel<<<G4, 256>>>(weight_ih, weight_hh, wh, wl);
    pack_cx_kernel<<<B_, 256>>>(cx, ch, cl);
    pack_transpose_kernel<<<dim3(H_ / 32, H_ / 32), dim3(32, 8)>>>(W_decomp, dh, dl);
    bias_kernel<<<G4 / 256, 256>>>(bias_ih, bias_hh, bias_p);

    // C_ST first (gates GEMM consumes it): [4096 x 1024] = tanh(cx @ Wd^T + b)
    tc_gemm_kernel<false><<<dim3(H_ / 128, B_ / 128), 512, SMEM_DYN>>>(
        ch, cl, dh, dl, KC, H_, b_decomp, nullptr, nullptr, nullptr, cst_p);

    // gates GEMM with fused T-LSTM epilogue: [4096 x 4096], interleaved n'
    tc_gemm_kernel<true><<<dim3(G4 / 128, B_ / 128), 512, SMEM_DYN>>>(
        ah, al, wh, wl, KG, G4, bias_p, t, cx, cst_p, out);
}

// round 7
// speedup vs baseline: 1.4091x; 1.0526x over previous
#include <cuda_runtime.h>
#include <cuda_bf16.h>
#include <cstdint>

// ---------------- problem dims ----------------
#define B_ 4096
#define I_ 512
#define H_ 1024
#define G4 4096
#define KG 1536   // gates GEMM K (512 + 1024)
#define KC 1024   // cst GEMM K

// ---------------- scratch (device globals; no allocs allowed) ----------------
__device__ float g_cst[(size_t)B_ * H_];
__device__ float g_bias[G4];                      // interleaved bias
__device__ __nv_bfloat16 gA_hi[(size_t)B_ * KG];
__device__ __nv_bfloat16 gA_lo[(size_t)B_ * KG];
__device__ __nv_bfloat16 gW_hi[(size_t)G4 * KG]; // interleaved rows n' = 4h+g
__device__ __nv_bfloat16 gW_lo[(size_t)G4 * KG];
__device__ __nv_bfloat16 gCx_hi[(size_t)B_ * KC];
__device__ __nv_bfloat16 gCx_lo[(size_t)B_ * KC];
__device__ __nv_bfloat16 gWd_hi[(size_t)H_ * KC];
__device__ __nv_bfloat16 gWd_lo[(size_t)H_ * KC];
__device__ unsigned int g_tile_ctr;
__device__ unsigned int g_cst_flag[256];

// ---------------- low-level helpers ----------------
__device__ __forceinline__ uint32_t smem_u32(const void* p) {
    uint32_t a;
    asm("{ .reg .u64 t; cvta.to.shared.u64 t, %1; cvt.u32.u64 %0, t; }" : "=r"(a) : "l"(p));
    return a;
}
__device__ __forceinline__ void cp16(uint32_t dst, const void* src) {
    asm volatile("cp.async.cg.shared.global [%0], [%1], 16;" :: "r"(dst), "l"(src));
}
#define CP_COMMIT() asm volatile("cp.async.commit_group;" ::: "memory")
#define CP_WAIT1()  asm volatile("cp.async.wait_group 1;" ::: "memory")

__device__ __forceinline__ void ldm_x4(uint32_t& r0, uint32_t& r1, uint32_t& r2, uint32_t& r3,
                                       uint32_t addr) {
    asm volatile("ldmatrix.sync.aligned.m8n8.x4.shared.b16 {%0,%1,%2,%3}, [%4];"
                 : "=r"(r0), "=r"(r1), "=r"(r2), "=r"(r3) : "r"(addr));
}
__device__ __forceinline__ void mma_bf16(float* c, const uint32_t* a, const uint32_t* b) {
    asm volatile(
        "mma.sync.aligned.m16n8k16.row.col.f32.bf16.bf16.f32 "
        "{%0,%1,%2,%3}, {%4,%5,%6,%7}, {%8,%9}, {%0,%1,%2,%3};"
        : "+f"(c[0]), "+f"(c[1]), "+f"(c[2]), "+f"(c[3])
        : "r"(a[0]), "r"(a[1]), "r"(a[2]), "r"(a[3]), "r"(b[0]), "r"(b[1]));
}
__device__ __forceinline__ float sigmoidf_(float x) { return 1.0f / (1.0f + expf(-x)); }

// ---------------- GEMM tiling ----------------
// CTA tile 128x128, BKE=64 (128B/row + 16B pad). 16 warps (512 thr), warp tile 32x32.
#define BKE 64
#define ROWB 144
#define TILEB (128 * ROWB)   // 18432
#define OFF_AH 0
#define OFF_AL TILEB
#define OFF_BH (2 * TILEB)
#define OFF_BL (3 * TILEB)
#define STAGEB (4 * TILEB)   // 73728
#define NSTG 3
#define SMEM_DYN (NSTG * STAGEB)   // 221184

// One stage: 4 tiles x 1024 cp16 chunks / 512 threads = 8 cp16 per thread.
__device__ __forceinline__ void load_stage(
    uint32_t sb,
    const __nv_bfloat16* __restrict__ Ahi, const __nv_bfloat16* __restrict__ Alo,
    const __nv_bfloat16* __restrict__ Bhi, const __nv_bfloat16* __restrict__ Blo,
    int mBase, int nBase, int k0, int Ktot, int tid)
{
    #pragma unroll
    for (int i = 0; i < 2; ++i) {
        const int id  = tid + i * 512;      // 0..1023
        const int row = id >> 3;            // 0..127
        const int c   = id & 7;             // 16B chunk within 128B row
        const uint32_t doff = row * ROWB + c * 16;
        const size_t aoff = (size_t)(mBase + row) * Ktot + k0 + c * 8;
        const size_t boff = (size_t)(nBase + row) * Ktot + k0 + c * 8;
        cp16(sb + OFF_AH + doff, Ahi + aoff);
        cp16(sb + OFF_AL + doff, Alo + aoff);
        cp16(sb + OFF_BH + doff, Bhi + boff);
        cp16(sb + OFF_BL + doff, Blo + boff);
    }
}

// 3-term bf16 mainloop over one 128x128 tile. Caller MUST __syncthreads() before
// reusing any stage smem after return (no trailing barrier here).
__device__ __forceinline__ void run_mainloop(
    uint32_t smem_base, int tid, int wid, int lane,
    const __nv_bfloat16* __restrict__ Ahi, const __nv_bfloat16* __restrict__ Alo,
    const __nv_bfloat16* __restrict__ Bhi, const __nv_bfloat16* __restrict__ Blo,
    int Ktot, int mBase, int nBase, float acc[2][4][4])
{
    const int wm = (wid & 3) * 32;
    const int wn = (wid >> 2) * 32;

    load_stage(smem_base, Ahi, Alo, Bhi, Blo, mBase, nBase, 0, Ktot, tid);
    CP_COMMIT();
    load_stage(smem_base + STAGEB, Ahi, Alo, Bhi, Blo, mBase, nBase, BKE, Ktot, tid);
    CP_COMMIT();

    const int aRow = wm + (lane & 15);
    const int aCol = (lane & 16);
    const int bRow = wn + (lane & 7) + ((lane & 16) >> 1);
    const int bCol = (lane & 8) << 1;

    const int nchunks = Ktot / BKE;
    int buf = 0;
    for (int c = 0; c < nchunks; ++c) {
        CP_WAIT1();          // own groups for chunks <= c complete
        __syncthreads();     // chunk c visible everywhere; chunk c-1's buffer reusable
        {
            const int nb = (buf + 2 >= NSTG) ? buf - 1 : buf + 2;   // (buf+2)%3
            if (c + 2 < nchunks)
                load_stage(smem_base + nb * STAGEB, Ahi, Alo, Bhi, Blo,
                           mBase, nBase, (c + 2) * BKE, Ktot, tid);
            CP_COMMIT();     // empty group when out of range keeps accounting aligned
        }

        const uint32_t sb = smem_base + buf * STAGEB;
        #pragma unroll
        for (int ks = 0; ks < 4; ++ks) {
            const int kb = ks * 32;
            uint32_t ah[2][4], al[2][4], bh[2][4], bl[2][4];
            #pragma unroll
            for (int mt = 0; mt < 2; ++mt) {
                const uint32_t ad = sb + (aRow + mt * 16) * ROWB + kb + aCol;
                ldm_x4(ah[mt][0], ah[mt][1], ah[mt][2], ah[mt][3], ad + OFF_AH);
                ldm_x4(al[mt][0], al[mt][1], al[mt][2], al[mt][3], ad + OFF_AL);
            }
            #pragma unroll
            for (int nt = 0; nt < 2; ++nt) {
                const uint32_t bd = sb + (bRow + nt * 16) * ROWB + kb + bCol;
                ldm_x4(bh[nt][0], bh[nt][1], bh[nt][2], bh[nt][3], bd + OFF_BH);
                ldm_x4(bl[nt][0], bl[nt][1], bl[nt][2], bl[nt][3], bd + OFF_BL);
            }
            #pragma unroll
            for (int mt = 0; mt < 2; ++mt)
                #pragma unroll
                for (int nt = 0; nt < 4; ++nt)
                    mma_bf16(acc[mt][nt], ah[mt], &bh[nt >> 1][(nt & 1) * 2]);
            #pragma unroll
            for (int mt = 0; mt < 2; ++mt)
                #pragma unroll
                for (int nt = 0; nt < 4; ++nt)
                    mma_bf16(acc[mt][nt], al[mt], &bh[nt >> 1][(nt & 1) * 2]);
            #pragma unroll
            for (int mt = 0; mt < 2; ++mt)
                #pragma unroll
                for (int nt = 0; nt < 4; ++nt)
                    mma_bf16(acc[mt][nt], ah[mt], &bl[nt >> 1][(nt & 1) * 2]);
        }
        buf = (buf + 1 == NSTG) ? 0 : buf + 1;
    }
}

// ---------------- persistent fused GEMM kernel ----------------
// Tiles 0..255: cst GEMM (g_cst = tanh(cx @ Wd^T + b_decomp)), sets done-flag.
// Tiles 256..1279: gates GEMM + fused T-LSTM epilogue (spins on its cst flag).
__global__ __launch_bounds__(512, 1) void fused_gemm_kernel(
    const float* __restrict__ tvec, const float* __restrict__ cx,
    const float* __restrict__ b_decomp, float* __restrict__ out)
{
    extern __shared__ char smem[];
    const uint32_t smem_base = smem_u32(smem);
    const int tid = threadIdx.x;
    const int wid = tid >> 5, lane = tid & 31;
    const int wm = (wid & 3) * 32;
    const int wn = (wid >> 2) * 32;
    const int rq = lane >> 2, cq = (lane & 3) * 2;
    __shared__ unsigned int s_tile;

    for (;;) {
        __syncthreads();                       // smem quiesced from previous tile
        if (tid == 0) s_tile = atomicAdd(&g_tile_ctr, 1u);
        __syncthreads();
        const unsigned int t = s_tile;
        if (t >= 1280u) return;

        float acc[2][4][4];
        #pragma unroll
        for (int i = 0; i < 2; ++i)
            #pragma unroll
            for (int j = 0; j < 4; ++j)
                #pragma unroll
                for (int q = 0; q < 4; ++q) acc[i][j][q] = 0.0f;

        if (t < 256u) {
            // ---- cst tile ----
            const int bx = t & 7, by = t >> 3;
            const int mBase = by * 128, nBase = bx * 128;
            run_mainloop(smem_base, tid, wid, lane, gCx_hi, gCx_lo, gWd_hi, gWd_lo,
                         KC, mBase, nBase, acc);
            // epilogue: tanh(acc + b_decomp[col]) -> g_cst (direct global stores)
            #pragma unroll
            for (int mt = 0; mt < 2; ++mt) {
                const int row0 = mBase + wm + mt * 16 + rq;
                #pragma unroll
                for (int nt = 0; nt < 4; ++nt) {
                    const int col = nBase + wn + nt * 8 + cq;
                    const float b0 = b_decomp[col], b1 = b_decomp[col + 1];
                    float2 v0 = make_float2(tanhf(acc[mt][nt][0] + b0),
                                            tanhf(acc[mt][nt][1] + b1));
                    float2 v1 = make_float2(tanhf(acc[mt][nt][2] + b0),
                                            tanhf(acc[mt][nt][3] + b1));
                    *(float2*)&g_cst[(size_t)row0 * H_ + col]       = v0;
                    *(float2*)&g_cst[(size_t)(row0 + 8) * H_ + col] = v1;
                }
            }
            __threadfence();
            __syncthreads();
            if (tid == 0) atomicExch(&g_cst_flag[t], 1u);
        } else {
            // ---- gates tile with fused T-LSTM epilogue ----
            const unsigned int g = t - 256u;
            const int bx = g & 31, by = g >> 5;
            const int mBase = by * 128, nBase = bx * 128;
            run_mainloop(smem_base, tid, wid, lane, gA_hi, gA_lo, gW_hi, gW_lo,
                         KG, mBase, nBase, acc);
            // wait for the cst tile this epilogue reads
            if (tid == 0) {
                while (atomicAdd(&g_cst_flag[(by << 3) + (bx >> 2)], 0u) == 0u)
                    __nanosleep(64);
                __threadfence();
            }
            __syncthreads();   // also: mainloop smem dead -> stage2 reusable for staging

            float* s_hy = (float*)(smem + 2 * STAGEB);   // [128][33]
            float* s_cy = s_hy + 128 * 33;
            const bool even = !(lane & 1);
            #pragma unroll
            for (int mt = 0; mt < 2; ++mt) {
                #pragma unroll
                for (int nt = 0; nt < 4; ++nt) {
                    const int n0 = nBase + wn + nt * 8 + cq;
                    const float b0 = g_bias[n0], b1 = g_bias[n0 + 1];
                    const float c0 = acc[mt][nt][0] + b0, c1 = acc[mt][nt][1] + b1;
                    const float c2 = acc[mt][nt][2] + b0, c3 = acc[mt][nt][3] + b1;
                    const float x = __shfl_xor_sync(0xffffffffu, even ? c2 : c0, 1);
                    const float y = __shfl_xor_sync(0xffffffffu, even ? c3 : c1, 1);
                    float ig, fg, cg, og;
                    if (even) { ig = c0; fg = c1; cg = x;  og = y;  }
                    else      { ig = x;  fg = y;  cg = c2; og = c3; }
                    const int row_l = wm + mt * 16 + rq + (even ? 0 : 8);
                    const int h_loc = (wn + nt * 8 + (cq & 4)) >> 2;
                    const int row = mBase + row_l;
                    const int h = (nBase >> 2) + h_loc;

                    const float tb = tvec[row];
                    const float T = (tb != 0.0f) ? (1.0f / tb) : 0.0f;
                    const float cs = __ldcg(&g_cst[(size_t)row * H_ + h]);
                    const float cc = cx[(size_t)row * H_ + h];
                    const float cadj = cc - cs + T * cs;
                    const float cyv = sigmoidf_(fg) * cadj + sigmoidf_(ig) * tanhf(cg);
                    const float hyv = sigmoidf_(og) * tanhf(cyv);
                    s_hy[row_l * 33 + h_loc] = hyv;
                    s_cy[row_l * 33 + h_loc] = cyv;
                }
            }
            __syncthreads();
            #pragma unroll
            for (int i = 0; i < 8; ++i) {
                const int idx = tid + i * 512;      // 0..4095
                const int r = idx >> 5, hh = idx & 31;
                const size_t o = (size_t)(mBase + r) * H_ + (nBase >> 2) + hh;
                out[o] = s_hy[r * 33 + hh];
                out[(size_t)B_ * H_ + o] = s_cy[r * 33 + hh];
            }
        }
    }
}

// ---------------- single fused pack kernel ----------------
__device__ __forceinline__ void split_bf16(float v, __nv_bfloat16& h, __nv_bfloat16& l) {
    h = __float2bfloat16(v);
    l = __float2bfloat16(v - __bfloat162float(h));
}

// blocks 0..4095: A rows [input|hx];  4096..8191: interleaved weights;
// 8192..12287: cx split;  12288..13311: Wd transpose+split;
// 13312: bias interleave + counter/flag reset.
__global__ __launch_bounds__(256) void pack_all_kernel(
    const float* __restrict__ input, const float* __restrict__ hx,
    const float* __restrict__ cx,
    const float* __restrict__ w_ih, const float* __restrict__ w_hh,
    const float* __restrict__ b_ih, const float* __restrict__ b_hh,
    const float* __restrict__ Wd)
{
    const int blk = blockIdx.x;
    const int tid = threadIdx.x;

    if (blk < 4096) {                       // pack A
        const int row = blk;
        #pragma unroll
        for (int i = 0; i < KG / 256; ++i) {
            const int k = tid + i * 256;
            const float v = (k < I_) ? input[(size_t)row * I_ + k]
                                     : hx[(size_t)row * H_ + (k - I_)];
            __nv_bfloat16 h, l; split_bf16(v, h, l);
            gA_hi[(size_t)row * KG + k] = h;
            gA_lo[(size_t)row * KG + k] = l;
        }
    } else if (blk < 8192) {                // pack W interleaved: n' = 4h+g
        const int np = blk - 4096;
        const int gg = np & 3, j = np >> 2;
        const int src = gg * H_ + j;
        #pragma unroll
        for (int i = 0; i < KG / 256; ++i) {
            const int k = tid + i * 256;
            const float v = (k < I_) ? w_ih[(size_t)src * I_ + k]
                                     : w_hh[(size_t)src * H_ + (k - I_)];
            __nv_bfloat16 h, l; split_bf16(v, h, l);
            gW_hi[(size_t)np * KG + k] = h;
            gW_lo[(size_t)np * KG + k] = l;
        }
    } else if (blk < 12288) {               // pack cx
        const int row = blk - 8192;
        #pragma unroll
        for (int i = 0; i < KC / 256; ++i) {
            const int k = tid + i * 256;
            const float v = cx[(size_t)row * KC + k];
            __nv_bfloat16 h, l; split_bf16(v, h, l);
            gCx_hi[(size_t)row * KC + k] = h;
            gCx_lo[(size_t)row * KC + k] = l;
        }
    } else if (blk < 13312) {               // Wd transpose + split
        __shared__ float tile[32][33];
        const int idx = blk - 12288;
        const int bx = (idx & 31) * 32, by = (idx >> 5) * 32;
        const int tx = tid & 31, ty = tid >> 5;    // 32 x 8
        #pragma unroll
        for (int i = 0; i < 32; i += 8)
            tile[ty + i][tx] = Wd[(size_t)(by + ty + i) * H_ + bx + tx];
        __syncthreads();
        #pragma unroll
        for (int i = 0; i < 32; i += 8) {
            const float v = tile[tx][ty + i];
            __nv_bfloat16 h, l; split_bf16(v, h, l);
            const size_t o = (size_t)(bx + ty + i) * KC + by + tx;
            gWd_hi[o] = h; gWd_lo[o] = l;
        }
    } else {                                // bias + reset
        #pragma unroll
        for (int i = 0; i < G4 / 256; ++i) {
            const int np = tid + i * 256;
            const int src = (np & 3) * H_ + (np >> 2);
            g_bias[np] = b_ih[src] + b_hh[src];
        }
        g_cst_flag[tid] = 0u;
        if (tid == 0) g_tile_ctr = 0u;
    }
}

// ---------------- launch ----------------
extern "C" void kernel_launch(void* const* d_in, const int* in_sizes, int n_in,
                              void* d_out, int out_size) {
    const float* input     = (const float*)d_in[0];
    const float* t         = (const float*)d_in[1];
    const float* hx        = (const float*)d_in[2];
    const float* cx        = (const float*)d_in[3];
    const float* weight_ih = (const float*)d_in[4];
    const float* weight_hh = (const float*)d_in[5];
    const float* bias_ih   = (const float*)d_in[6];
    const float* bias_hh   = (const float*)d_in[7];
    const float* W_decomp  = (const float*)d_in[8];
    const float* b_decomp  = (const float*)d_in[9];
    float* out = (float*)d_out;

    cudaFuncSetAttribute(fused_gemm_kernel,
                         cudaFuncAttributeMaxDynamicSharedMemorySize, SMEM_DYN);

    pack_all_kernel<<<13313, 256>>>(input, hx, cx, weight_ih, weight_hh,
                                    bias_ih, bias_hh, W_decomp);

    fused_gemm_kernel<<<152, 512, SMEM_DYN>>>(t, cx, b_decomp, out);
}